// round 1
// baseline (speedup 1.0000x reference)
#include <cuda_runtime.h>
#include <cuda_bf16.h>

#define NU 100000
#define NI 50000
#define NN 150000            // NU + NI
#define H  128
#define E  1000000
#define E2 2000000
#define NLAYERS 3
#define SLOPE 0.2f

#define SCAN_BS 1024
#define SCAN_NB ((NN + SCAN_BS - 1) / SCAN_BS)   // 147

// ---------- device scratch (static globals; no runtime allocation) ----------
__device__ int   g_deg[NN];
__device__ int   g_rp[NN + 1];
__device__ int   g_cursor[NN];
__device__ float g_dinv[NN];
__device__ int   g_partials[SCAN_NB + 1];
__device__ int2  g_edges[E2];          // (src, time) per CSR slot
__device__ float g_x[NN * H];          // current layer input
__device__ float g_agg[NN * H];        // aggregated messages

// ---------- graph build ----------
__global__ void k_zero_deg() {
    int i = blockIdx.x * blockDim.x + threadIdx.x;
    if (i < NN) g_deg[i] = 0;
}

__global__ void k_hist(const int* __restrict__ ui, const int* __restrict__ ii) {
    int e = blockIdx.x * blockDim.x + threadIdx.x;
    if (e < E) {
        atomicAdd(&g_deg[ui[e]], 1);
        atomicAdd(&g_deg[ii[e] + NU], 1);
    }
}

__global__ void k_scan1() {
    __shared__ int sh[SCAN_BS];
    int i = blockIdx.x * SCAN_BS + threadIdx.x;
    int v = (i < NN) ? g_deg[i] : 0;
    sh[threadIdx.x] = v;
    __syncthreads();
    for (int off = 1; off < SCAN_BS; off <<= 1) {
        int t = (threadIdx.x >= off) ? sh[threadIdx.x - off] : 0;
        __syncthreads();
        sh[threadIdx.x] += t;
        __syncthreads();
    }
    if (i < NN) g_rp[i] = sh[threadIdx.x] - v;  // exclusive
    if (threadIdx.x == SCAN_BS - 1) g_partials[blockIdx.x] = sh[SCAN_BS - 1];
}

__global__ void k_scan2() {
    if (threadIdx.x == 0 && blockIdx.x == 0) {
        int acc = 0;
        for (int i = 0; i < SCAN_NB; i++) {
            int t = g_partials[i];
            g_partials[i] = acc;
            acc += t;
        }
    }
}

__global__ void k_scan3() {
    int i = blockIdx.x * blockDim.x + threadIdx.x;
    if (i < NN) {
        int v = g_rp[i] + g_partials[i / SCAN_BS];
        g_rp[i] = v;
        g_cursor[i] = v;
        int d = g_deg[i];
        g_dinv[i] = rsqrtf((float)(d > 1 ? d : 1));
    }
    if (i == 0) g_rp[NN] = E2;
}

__global__ void k_scatter(const int* __restrict__ ui, const int* __restrict__ ii,
                          const int* __restrict__ ts) {
    int e = blockIdx.x * blockDim.x + threadIdx.x;
    if (e < E) {
        int u = ui[e];
        int it = ii[e] + NU;
        int t = ts[e];
        int p = atomicAdd(&g_cursor[u], 1);
        g_edges[p] = make_int2(it, t);
        int q = atomicAdd(&g_cursor[it], 1);
        g_edges[q] = make_int2(u, t);
    }
}

// ---------- init x and output column block 0 ----------
__global__ void k_init(const float* __restrict__ ue, const float* __restrict__ ie,
                       float* __restrict__ out) {
    int i = blockIdx.x * blockDim.x + threadIdx.x;
    if (i < NN * H) {
        int n = i >> 7;
        int j = i & 127;
        float v = (n < NU) ? ue[i] : ie[i - NU * H];
        g_x[i] = v;
        out[(long)n * (H * (NLAYERS + 1)) + j] = v;
    }
}

// ---------- aggregation: one warp per node, lane handles float4 (4 cols) ----------
__global__ void k_agg(const float* __restrict__ tt) {
    int gw = (blockIdx.x * blockDim.x + threadIdx.x) >> 5;
    int lane = threadIdx.x & 31;
    if (gw >= NN) return;
    int beg = g_rp[gw], end = g_rp[gw + 1];
    const float4* x4 = (const float4*)g_x;
    const float4* t4 = (const float4*)tt;
    float4 acc = make_float4(0.f, 0.f, 0.f, 0.f);
    for (int e = beg; e < end; e++) {
        int2 ent = g_edges[e];
        float w = g_dinv[ent.x];
        float4 xv = __ldg(&x4[ent.x * 32 + lane]);
        float4 tv = __ldg(&t4[ent.y * 32 + lane]);
        acc.x = fmaf((xv.x + tv.x), w, acc.x);
        acc.y = fmaf((xv.y + tv.y), w, acc.y);
        acc.z = fmaf((xv.z + tv.z), w, acc.z);
        acc.w = fmaf((xv.w + tv.w), w, acc.w);
    }
    float wn = g_dinv[gw];
    float4 r = make_float4(acc.x * wn, acc.y * wn, acc.z * wn, acc.w * wn);
    ((float4*)g_agg)[gw * 32 + lane] = r;
}

// ---------- fused GEMM + bias + leaky_relu + l2norm + writes ----------
// block: 128 threads, tile 64 rows x 128 cols, 8x8 micro-tile per thread
__global__ void __launch_bounds__(128) k_gemm(const float* __restrict__ W,
                                              const float* __restrict__ bias,
                                              float* __restrict__ out, int outoff) {
    __shared__ float Ws[32][128];
    __shared__ float As[32][68];   // padded: 68 floats stride keeps 16B align + bank spread
    __shared__ float rn[64];

    int tid = threadIdx.x;
    int tx = tid & 15;        // col group: cols tx*8 .. tx*8+7
    int ty = tid >> 4;        // row group: rows ty*8 .. ty*8+7
    int row0 = blockIdx.x * 64;

    float acc[8][8];
#pragma unroll
    for (int i = 0; i < 8; i++)
#pragma unroll
        for (int j = 0; j < 8; j++) acc[i][j] = 0.f;

    for (int kk = 0; kk < H; kk += 32) {
        __syncthreads();
        // load W chunk: rows kk..kk+31 of [128x128], 1024 float4 / 128 thr = 8 each
        for (int i = tid; i < 32 * 32; i += 128) {
            int k = i >> 5, c4 = i & 31;
            ((float4*)&Ws[k][0])[c4] = ((const float4*)(W + (kk + k) * H))[c4];
        }
        // load A chunk transposed: 64 rows x 8 float4 = 512 / 128 thr = 4 each
        for (int i = tid; i < 64 * 8; i += 128) {
            int r = i >> 3, kq = i & 7;
            int grow = row0 + r;
            float4 v = make_float4(0.f, 0.f, 0.f, 0.f);
            if (grow < NN) v = ((const float4*)(g_agg + (long)grow * H))[(kk >> 2) + kq];
            As[kq * 4 + 0][r] = v.x;
            As[kq * 4 + 1][r] = v.y;
            As[kq * 4 + 2][r] = v.z;
            As[kq * 4 + 3][r] = v.w;
        }
        __syncthreads();
#pragma unroll 4
        for (int k = 0; k < 32; k++) {
            float4 a0 = *(const float4*)&As[k][ty * 8];
            float4 a1 = *(const float4*)&As[k][ty * 8 + 4];
            float4 w0 = *(const float4*)&Ws[k][tx * 8];
            float4 w1 = *(const float4*)&Ws[k][tx * 8 + 4];
            float av[8] = {a0.x, a0.y, a0.z, a0.w, a1.x, a1.y, a1.z, a1.w};
            float wv[8] = {w0.x, w0.y, w0.z, w0.w, w1.x, w1.y, w1.z, w1.w};
#pragma unroll
            for (int i = 0; i < 8; i++)
#pragma unroll
                for (int j = 0; j < 8; j++) acc[i][j] = fmaf(av[i], wv[j], acc[i][j]);
        }
    }

    // bias + leaky relu, accumulate row sum of squares
    float bv[8];
#pragma unroll
    for (int j = 0; j < 8; j++) bv[j] = bias[tx * 8 + j];

    __syncthreads();
    if (tid < 64) rn[tid] = 0.f;
    __syncthreads();

#pragma unroll
    for (int i = 0; i < 8; i++) {
        float ps = 0.f;
#pragma unroll
        for (int j = 0; j < 8; j++) {
            float h = acc[i][j] + bv[j];
            h = (h >= 0.f) ? h : SLOPE * h;
            acc[i][j] = h;
            ps = fmaf(h, h, ps);
        }
        atomicAdd(&rn[ty * 8 + i], ps);
    }
    __syncthreads();

#pragma unroll
    for (int i = 0; i < 8; i++) {
        int lrow = ty * 8 + i;
        int grow = row0 + lrow;
        if (grow < NN) {
            float nrm = sqrtf(rn[lrow]);
            float rinv = 1.f / fmaxf(nrm, 1e-12f);
            float4 h0 = make_float4(acc[i][0], acc[i][1], acc[i][2], acc[i][3]);
            float4 h1 = make_float4(acc[i][4], acc[i][5], acc[i][6], acc[i][7]);
            // next-layer input (unnormalized)
            float* xr = g_x + (long)grow * H + tx * 8;
            *(float4*)xr = h0;
            *(float4*)(xr + 4) = h1;
            // normalized output
            float* orow = out + (long)grow * (H * (NLAYERS + 1)) + outoff + tx * 8;
            float4 o0 = make_float4(h0.x * rinv, h0.y * rinv, h0.z * rinv, h0.w * rinv);
            float4 o1 = make_float4(h1.x * rinv, h1.y * rinv, h1.z * rinv, h1.w * rinv);
            *(float4*)orow = o0;
            *(float4*)(orow + 4) = o1;
        }
    }
}

extern "C" void kernel_launch(void* const* d_in, const int* in_sizes, int n_in,
                              void* d_out, int out_size) {
    const float* user_embd  = (const float*)d_in[0];
    const float* item_embd  = (const float*)d_in[1];
    const float* time_table = (const float*)d_in[2];
    const float* W          = (const float*)d_in[3];
    const float* b          = (const float*)d_in[4];
    const int*   user_idx   = (const int*)d_in[5];
    const int*   item_idx   = (const int*)d_in[6];
    const int*   time_seq   = (const int*)d_in[7];
    float* out = (float*)d_out;

    // graph build
    k_zero_deg<<<(NN + 255) / 256, 256>>>();
    k_hist<<<(E + 255) / 256, 256>>>(user_idx, item_idx);
    k_scan1<<<SCAN_NB, SCAN_BS>>>();
    k_scan2<<<1, 32>>>();
    k_scan3<<<(NN + 255) / 256, 256>>>();
    k_scatter<<<(E + 255) / 256, 256>>>(user_idx, item_idx, time_seq);

    // init x and first 128 output columns
    k_init<<<(NN * H + 255) / 256, 256>>>(user_embd, item_embd, out);

    // layers
    for (int l = 0; l < NLAYERS; l++) {
        k_agg<<<(NN * 32 + 255) / 256, 256>>>(time_table);
        k_gemm<<<(NN + 63) / 64, 128>>>(W + (long)l * H * H, b + (long)l * H,
                                        out, (l + 1) * H);
    }
}

// round 2
// speedup vs baseline: 1.1568x; 1.1568x over previous
#include <cuda_runtime.h>
#include <cuda_fp16.h>
#include <cuda_bf16.h>

#define NU 100000
#define NI 50000
#define NN 150000            // NU + NI
#define H  128
#define E  1000000
#define E2 2000000
#define NLAYERS 3
#define SLOPE 0.2f

#define SCAN_BS 1024
#define SCAN_NB ((NN + SCAN_BS - 1) / SCAN_BS)   // 147

// ---------- device scratch (static globals; no runtime allocation) ----------
__device__ int   g_deg[NN];
__device__ int   g_rp[NN + 1];
__device__ int   g_cursor[NN];
__device__ float g_dinv[NN];
__device__ int   g_partials[SCAN_NB + 1];
__device__ int2  g_edge2[E2];          // (src | t<<18, bits(dinv[src])) per CSR slot
__device__ __half g_xh[NN * H];        // current layer input, fp16 (gather format)
__device__ float g_T[NN * H];          // precomputed time aggregation (layer-invariant)
__device__ float g_agg[NN * H];        // aggregated messages (GEMM input)

// ---------- graph build ----------
__global__ void k_zero_deg() {
    int i = blockIdx.x * blockDim.x + threadIdx.x;
    if (i < NN) g_deg[i] = 0;
}

__global__ void k_hist(const int* __restrict__ ui, const int* __restrict__ ii) {
    int e = blockIdx.x * blockDim.x + threadIdx.x;
    if (e < E) {
        atomicAdd(&g_deg[ui[e]], 1);
        atomicAdd(&g_deg[ii[e] + NU], 1);
    }
}

__global__ void k_scan1() {
    __shared__ int sh[SCAN_BS];
    int i = blockIdx.x * SCAN_BS + threadIdx.x;
    int v = (i < NN) ? g_deg[i] : 0;
    sh[threadIdx.x] = v;
    __syncthreads();
    for (int off = 1; off < SCAN_BS; off <<= 1) {
        int t = (threadIdx.x >= off) ? sh[threadIdx.x - off] : 0;
        __syncthreads();
        sh[threadIdx.x] += t;
        __syncthreads();
    }
    if (i < NN) g_rp[i] = sh[threadIdx.x] - v;  // exclusive within block
    if (threadIdx.x == SCAN_BS - 1) g_partials[blockIdx.x] = sh[SCAN_BS - 1];
}

// parallel exclusive scan of the 147 block partials (one block)
__global__ void k_scan2() {
    __shared__ int sh[256];
    int i = threadIdx.x;
    int v = (i < SCAN_NB) ? g_partials[i] : 0;
    sh[i] = v;
    __syncthreads();
    for (int off = 1; off < 256; off <<= 1) {
        int t = (i >= off) ? sh[i - off] : 0;
        __syncthreads();
        sh[i] += t;
        __syncthreads();
    }
    if (i < SCAN_NB) g_partials[i] = sh[i] - v;  // exclusive
}

__global__ void k_scan3() {
    int i = blockIdx.x * blockDim.x + threadIdx.x;
    if (i < NN) {
        int v = g_rp[i] + g_partials[i / SCAN_BS];
        g_rp[i] = v;
        g_cursor[i] = v;
        int d = g_deg[i];
        g_dinv[i] = rsqrtf((float)(d > 1 ? d : 1));
    }
    if (i == 0) g_rp[NN] = E2;
}

__global__ void k_scatter(const int* __restrict__ ui, const int* __restrict__ ii,
                          const int* __restrict__ ts) {
    int e = blockIdx.x * blockDim.x + threadIdx.x;
    if (e < E) {
        int u = ui[e];
        int it = ii[e] + NU;
        int t = ts[e];
        float wu = g_dinv[u];
        float wi = g_dinv[it];
        int p = atomicAdd(&g_cursor[u], 1);
        g_edge2[p] = make_int2(it | (t << 18), __float_as_int(wi));
        int q = atomicAdd(&g_cursor[it], 1);
        g_edge2[q] = make_int2(u | (t << 18), __float_as_int(wu));
    }
}

// ---------- init: fp16 gather copy of x, fp32 output block 0 ----------
__global__ void k_init(const float* __restrict__ ue, const float* __restrict__ ie,
                       float* __restrict__ out) {
    int i = blockIdx.x * blockDim.x + threadIdx.x;
    if (i < NN * H) {
        int n = i >> 7;
        int j = i & 127;
        float v = (n < NU) ? ue[i] : ie[i - NU * H];
        g_xh[i] = __float2half(v);
        out[(long)n * (H * (NLAYERS + 1)) + j] = v;
    }
}

// ---------- one-time: T[dst] = sum_e dinv[src] * tt[t_e]   (warp per node) ----------
__global__ void k_aggT(const float* __restrict__ tt) {
    int gw = (blockIdx.x * blockDim.x + threadIdx.x) >> 5;
    int lane = threadIdx.x & 31;
    if (gw >= NN) return;
    int beg = g_rp[gw], end = g_rp[gw + 1];
    const float4* t4 = (const float4*)tt;
    float4 acc = make_float4(0.f, 0.f, 0.f, 0.f);
    for (int e = beg; e < end; e++) {
        int2 ed = g_edge2[e];
        int t = ed.x >> 18;
        float w = __int_as_float(ed.y);
        float4 tv = __ldg(&t4[t * 32 + lane]);
        acc.x = fmaf(tv.x, w, acc.x);
        acc.y = fmaf(tv.y, w, acc.y);
        acc.z = fmaf(tv.z, w, acc.z);
        acc.w = fmaf(tv.w, w, acc.w);
    }
    ((float4*)g_T)[gw * 32 + lane] = acc;
}

// ---------- per-layer: agg[dst] = dinv[dst]*(sum_e w*xh[src] + T[dst]) ----------
// half-warp per node; each of 16 lanes owns 8 columns (one uint4 = 8 halves)
__global__ void k_aggx() {
    int gt = blockIdx.x * blockDim.x + threadIdx.x;
    int n = gt >> 4;           // node = global half-warp index
    int sl = gt & 15;          // sub-lane 0..15
    if (n >= NN) return;
    int beg = g_rp[n], end = g_rp[n + 1];
    const uint4* xh4 = (const uint4*)g_xh;   // 16 uint4 per row
    float acc0 = 0.f, acc1 = 0.f, acc2 = 0.f, acc3 = 0.f;
    float acc4 = 0.f, acc5 = 0.f, acc6 = 0.f, acc7 = 0.f;
    for (int e = beg; e < end; e++) {
        int2 ed = __ldg(&g_edge2[e]);
        int src = ed.x & 0x3FFFF;
        float w = __int_as_float(ed.y);
        uint4 v = __ldg(&xh4[src * 16 + sl]);
        float2 f0 = __half22float2(*(const __half2*)&v.x);
        float2 f1 = __half22float2(*(const __half2*)&v.y);
        float2 f2 = __half22float2(*(const __half2*)&v.z);
        float2 f3 = __half22float2(*(const __half2*)&v.w);
        acc0 = fmaf(f0.x, w, acc0); acc1 = fmaf(f0.y, w, acc1);
        acc2 = fmaf(f1.x, w, acc2); acc3 = fmaf(f1.y, w, acc3);
        acc4 = fmaf(f2.x, w, acc4); acc5 = fmaf(f2.y, w, acc5);
        acc6 = fmaf(f3.x, w, acc6); acc7 = fmaf(f3.y, w, acc7);
    }
    float wn = g_dinv[n];
    const float4* Trow = (const float4*)(g_T + (long)n * H);
    float4 t0 = Trow[sl * 2];
    float4 t1 = Trow[sl * 2 + 1];
    float4 r0 = make_float4(wn * (acc0 + t0.x), wn * (acc1 + t0.y),
                            wn * (acc2 + t0.z), wn * (acc3 + t0.w));
    float4 r1 = make_float4(wn * (acc4 + t1.x), wn * (acc5 + t1.y),
                            wn * (acc6 + t1.z), wn * (acc7 + t1.w));
    float4* arow = (float4*)(g_agg + (long)n * H);
    arow[sl * 2] = r0;
    arow[sl * 2 + 1] = r1;
}

// ---------- fused GEMM + bias + leaky_relu + l2norm + writes ----------
// block: 128 threads, tile 64 rows x 128 cols, 8x8 micro-tile per thread
__global__ void __launch_bounds__(128) k_gemm(const float* __restrict__ W,
                                              const float* __restrict__ bias,
                                              float* __restrict__ out, int outoff) {
    __shared__ float Ws[32][128];
    __shared__ float As[32][68];
    __shared__ float rn[64];

    int tid = threadIdx.x;
    int tx = tid & 15;        // col group: cols tx*8 .. tx*8+7
    int ty = tid >> 4;        // row group: rows ty*8 .. ty*8+7
    int row0 = blockIdx.x * 64;

    float acc[8][8];
#pragma unroll
    for (int i = 0; i < 8; i++)
#pragma unroll
        for (int j = 0; j < 8; j++) acc[i][j] = 0.f;

    for (int kk = 0; kk < H; kk += 32) {
        __syncthreads();
        for (int i = tid; i < 32 * 32; i += 128) {
            int k = i >> 5, c4 = i & 31;
            ((float4*)&Ws[k][0])[c4] = ((const float4*)(W + (kk + k) * H))[c4];
        }
        for (int i = tid; i < 64 * 8; i += 128) {
            int r = i >> 3, kq = i & 7;
            int grow = row0 + r;
            float4 v = make_float4(0.f, 0.f, 0.f, 0.f);
            if (grow < NN) v = ((const float4*)(g_agg + (long)grow * H))[(kk >> 2) + kq];
            As[kq * 4 + 0][r] = v.x;
            As[kq * 4 + 1][r] = v.y;
            As[kq * 4 + 2][r] = v.z;
            As[kq * 4 + 3][r] = v.w;
        }
        __syncthreads();
#pragma unroll 4
        for (int k = 0; k < 32; k++) {
            float4 a0 = *(const float4*)&As[k][ty * 8];
            float4 a1 = *(const float4*)&As[k][ty * 8 + 4];
            float4 w0 = *(const float4*)&Ws[k][tx * 8];
            float4 w1 = *(const float4*)&Ws[k][tx * 8 + 4];
            float av[8] = {a0.x, a0.y, a0.z, a0.w, a1.x, a1.y, a1.z, a1.w};
            float wv[8] = {w0.x, w0.y, w0.z, w0.w, w1.x, w1.y, w1.z, w1.w};
#pragma unroll
            for (int i = 0; i < 8; i++)
#pragma unroll
                for (int j = 0; j < 8; j++) acc[i][j] = fmaf(av[i], wv[j], acc[i][j]);
        }
    }

    float bv[8];
#pragma unroll
    for (int j = 0; j < 8; j++) bv[j] = bias[tx * 8 + j];

    __syncthreads();
    if (tid < 64) rn[tid] = 0.f;
    __syncthreads();

#pragma unroll
    for (int i = 0; i < 8; i++) {
        float ps = 0.f;
#pragma unroll
        for (int j = 0; j < 8; j++) {
            float h = acc[i][j] + bv[j];
            h = (h >= 0.f) ? h : SLOPE * h;
            acc[i][j] = h;
            ps = fmaf(h, h, ps);
        }
        atomicAdd(&rn[ty * 8 + i], ps);
    }
    __syncthreads();

#pragma unroll
    for (int i = 0; i < 8; i++) {
        int lrow = ty * 8 + i;
        int grow = row0 + lrow;
        if (grow < NN) {
            float nrm = sqrtf(rn[lrow]);
            float rinv = 1.f / fmaxf(nrm, 1e-12f);
            // next-layer input (unnormalized), fp16 gather format: 8 halves = uint4
            __half2 h01 = __floats2half2_rn(acc[i][0], acc[i][1]);
            __half2 h23 = __floats2half2_rn(acc[i][2], acc[i][3]);
            __half2 h45 = __floats2half2_rn(acc[i][4], acc[i][5]);
            __half2 h67 = __floats2half2_rn(acc[i][6], acc[i][7]);
            uint4 hv;
            hv.x = *(unsigned*)&h01; hv.y = *(unsigned*)&h23;
            hv.z = *(unsigned*)&h45; hv.w = *(unsigned*)&h67;
            ((uint4*)(g_xh + (long)grow * H))[tx] = hv;
            // normalized output
            float* orow = out + (long)grow * (H * (NLAYERS + 1)) + outoff + tx * 8;
            float4 o0 = make_float4(acc[i][0] * rinv, acc[i][1] * rinv,
                                    acc[i][2] * rinv, acc[i][3] * rinv);
            float4 o1 = make_float4(acc[i][4] * rinv, acc[i][5] * rinv,
                                    acc[i][6] * rinv, acc[i][7] * rinv);
            *(float4*)orow = o0;
            *(float4*)(orow + 4) = o1;
        }
    }
}

extern "C" void kernel_launch(void* const* d_in, const int* in_sizes, int n_in,
                              void* d_out, int out_size) {
    const float* user_embd  = (const float*)d_in[0];
    const float* item_embd  = (const float*)d_in[1];
    const float* time_table = (const float*)d_in[2];
    const float* W          = (const float*)d_in[3];
    const float* b          = (const float*)d_in[4];
    const int*   user_idx   = (const int*)d_in[5];
    const int*   item_idx   = (const int*)d_in[6];
    const int*   time_seq   = (const int*)d_in[7];
    float* out = (float*)d_out;

    // graph build
    k_zero_deg<<<(NN + 255) / 256, 256>>>();
    k_hist<<<(E + 255) / 256, 256>>>(user_idx, item_idx);
    k_scan1<<<SCAN_NB, SCAN_BS>>>();
    k_scan2<<<1, 256>>>();
    k_scan3<<<(NN + 255) / 256, 256>>>();
    k_scatter<<<(E + 255) / 256, 256>>>(user_idx, item_idx, time_seq);

    // init x (fp16) and first 128 output columns (fp32)
    k_init<<<(NN * H + 255) / 256, 256>>>(user_embd, item_embd, out);

    // layer-invariant time aggregation
    k_aggT<<<(NN * 32 + 255) / 256, 256>>>(time_table);

    // layers
    for (int l = 0; l < NLAYERS; l++) {
        k_aggx<<<(NN * 16 + 255) / 256, 256>>>();
        k_gemm<<<(NN + 63) / 64, 128>>>(W + (long)l * H * H, b + (long)l * H,
                                        out, (l + 1) * H);
    }
}

// round 5
// speedup vs baseline: 1.8176x; 1.5711x over previous
#include <cuda_runtime.h>
#include <cuda_fp16.h>
#include <cuda_bf16.h>

#define NU 100000
#define NI 50000
#define NN 150000
#define HD 128
#define NE 1000000
#define NE2 2000000
#define NL 3
#define SLOPE 0.2f
#define OW 512

#define SCAN_BS 1024
#define SCAN_NB 147

// ---------- device scratch ----------
__device__ int    g_deg[NN];
__device__ int    g_rp[NN + 1];
__device__ int    g_cursor[NN];
__device__ float  g_dinv[NN];
__device__ int    g_partials[SCAN_NB + 1];
__device__ int2   g_edge2[NE2];
__device__ __half g_xh[NN * HD];
__device__ __half g_aggh[NN * HD];
__device__ float  g_T[NN * HD];
__device__ __half g_Wh[NL * HD * HD];

// ---------- mma helpers ----------
__device__ __forceinline__ unsigned smem_u32(const void* p) {
    return (unsigned)__cvta_generic_to_shared(p);
}

__device__ __forceinline__ void ldsm_x4(unsigned& r0, unsigned& r1,
                                        unsigned& r2, unsigned& r3, unsigned a) {
    asm volatile("ldmatrix.sync.aligned.m8n8.x4.shared.b16 {%0,%1,%2,%3}, [%4];"
                 : "=r"(r0), "=r"(r1), "=r"(r2), "=r"(r3) : "r"(a));
}

__device__ __forceinline__ void ldsm_x4_t(unsigned& r0, unsigned& r1,
                                          unsigned& r2, unsigned& r3, unsigned a) {
    asm volatile("ldmatrix.sync.aligned.m8n8.x4.trans.shared.b16 {%0,%1,%2,%3}, [%4];"
                 : "=r"(r0), "=r"(r1), "=r"(r2), "=r"(r3) : "r"(a));
}

__device__ __forceinline__ void mma16816(float* d, unsigned a0, unsigned a1,
                                         unsigned a2, unsigned a3,
                                         unsigned b0, unsigned b1) {
    asm volatile("mma.sync.aligned.m16n8k16.row.col.f32.f16.f16.f32 "
                 "{%0,%1,%2,%3}, {%4,%5,%6,%7}, {%8,%9}, {%0,%1,%2,%3};"
                 : "+f"(d[0]), "+f"(d[1]), "+f"(d[2]), "+f"(d[3])
                 : "r"(a0), "r"(a1), "r"(a2), "r"(a3), "r"(b0), "r"(b1));
}

__device__ __forceinline__ unsigned h2u(__half2 h) {
    unsigned u;
    memcpy(&u, &h, 4);
    return u;
}

// ---------- graph build ----------
__global__ void k_zero_deg() {
    int i = blockIdx.x * blockDim.x + threadIdx.x;
    if (i < NN) g_deg[i] = 0;
}

__global__ void k_hist(const int* __restrict__ ui, const int* __restrict__ ii) {
    int e = blockIdx.x * blockDim.x + threadIdx.x;
    if (e < NE) {
        atomicAdd(&g_deg[ui[e]], 1);
        atomicAdd(&g_deg[ii[e] + NU], 1);
    }
}

__global__ void k_scan1() {
    __shared__ int sh[SCAN_BS];
    int i = blockIdx.x * SCAN_BS + threadIdx.x;
    int v = (i < NN) ? g_deg[i] : 0;
    sh[threadIdx.x] = v;
    __syncthreads();
    for (int off = 1; off < SCAN_BS; off <<= 1) {
        int t = (threadIdx.x >= off) ? sh[threadIdx.x - off] : 0;
        __syncthreads();
        sh[threadIdx.x] += t;
        __syncthreads();
    }
    if (i < NN) g_rp[i] = sh[threadIdx.x] - v;
    if (threadIdx.x == SCAN_BS - 1) g_partials[blockIdx.x] = sh[SCAN_BS - 1];
}

__global__ void k_scan2() {
    __shared__ int sh[256];
    int i = threadIdx.x;
    int v = (i < SCAN_NB) ? g_partials[i] : 0;
    sh[i] = v;
    __syncthreads();
    for (int off = 1; off < 256; off <<= 1) {
        int t = (i >= off) ? sh[i - off] : 0;
        __syncthreads();
        sh[i] += t;
        __syncthreads();
    }
    if (i < SCAN_NB) g_partials[i] = sh[i] - v;
}

__global__ void k_scan3() {
    int i = blockIdx.x * blockDim.x + threadIdx.x;
    if (i < NN) {
        int v = g_rp[i] + g_partials[i / SCAN_BS];
        g_rp[i] = v;
        g_cursor[i] = v;
        int d = g_deg[i];
        g_dinv[i] = rsqrtf((float)(d > 1 ? d : 1));
    }
    if (i == 0) g_rp[NN] = NE2;
}

__global__ void k_scatter(const int* __restrict__ ui, const int* __restrict__ ii,
                          const int* __restrict__ ts) {
    int e = blockIdx.x * blockDim.x + threadIdx.x;
    if (e < NE) {
        int u = ui[e];
        int it = ii[e] + NU;
        int t = ts[e];
        float wu = g_dinv[u];
        float wi = g_dinv[it];
        int p = atomicAdd(&g_cursor[u], 1);
        g_edge2[p] = make_int2(it | (t << 18), __float_as_int(wi));
        int q = atomicAdd(&g_cursor[it], 1);
        g_edge2[q] = make_int2(u | (t << 18), __float_as_int(wu));
    }
}

// ---------- init ----------
__global__ void k_init(const float* __restrict__ ue, const float* __restrict__ ie,
                       const float* __restrict__ Wsrc, float* __restrict__ out) {
    int i = blockIdx.x * blockDim.x + threadIdx.x;
    if (i < NN * HD) {
        int n = i >> 7;
        int j = i & 127;
        float v = (n < NU) ? ue[i] : ie[i - NU * HD];
        g_xh[i] = __float2half(v);
        out[(long)n * OW + j] = v;
    }
    if (i < NL * HD * HD) {
        g_Wh[i] = __float2half(Wsrc[i]);
    }
}

// ---------- one-time time aggregation ----------
__global__ void k_aggT(const float* __restrict__ tt) {
    int gw = (blockIdx.x * blockDim.x + threadIdx.x) >> 5;
    int lane = threadIdx.x & 31;
    if (gw >= NN) return;
    int beg = g_rp[gw];
    int end = g_rp[gw + 1];
    const float4* t4 = (const float4*)tt;
    float4 acc = make_float4(0.f, 0.f, 0.f, 0.f);
    for (int e = beg; e < end; e++) {
        int2 ed = g_edge2[e];
        int t = ed.x >> 18;
        float w = __int_as_float(ed.y);
        float4 tv = __ldg(&t4[t * 32 + lane]);
        acc.x = fmaf(tv.x, w, acc.x);
        acc.y = fmaf(tv.y, w, acc.y);
        acc.z = fmaf(tv.z, w, acc.z);
        acc.w = fmaf(tv.w, w, acc.w);
    }
    ((float4*)g_T)[gw * 32 + lane] = acc;
}

// ---------- per-layer x aggregation (half-warp per node) ----------
__global__ void k_aggx() {
    int gt = blockIdx.x * blockDim.x + threadIdx.x;
    int n = gt >> 4;
    int sl = gt & 15;
    if (n >= NN) return;
    int beg = g_rp[n];
    int end = g_rp[n + 1];
    const uint4* xh4 = (const uint4*)g_xh;
    float a0 = 0.f, a1 = 0.f, a2 = 0.f, a3 = 0.f;
    float a4 = 0.f, a5 = 0.f, a6 = 0.f, a7 = 0.f;
    for (int e = beg; e < end; e++) {
        int2 ed = __ldg(&g_edge2[e]);
        int src = ed.x & 0x3FFFF;
        float w = __int_as_float(ed.y);
        uint4 v = __ldg(&xh4[src * 16 + sl]);
        float2 f0 = __half22float2(*(const __half2*)&v.x);
        float2 f1 = __half22float2(*(const __half2*)&v.y);
        float2 f2 = __half22float2(*(const __half2*)&v.z);
        float2 f3 = __half22float2(*(const __half2*)&v.w);
        a0 = fmaf(f0.x, w, a0);
        a1 = fmaf(f0.y, w, a1);
        a2 = fmaf(f1.x, w, a2);
        a3 = fmaf(f1.y, w, a3);
        a4 = fmaf(f2.x, w, a4);
        a5 = fmaf(f2.y, w, a5);
        a6 = fmaf(f3.x, w, a6);
        a7 = fmaf(f3.y, w, a7);
    }
    float wn = g_dinv[n];
    const float4* Trow = (const float4*)(g_T + (long)n * HD);
    float4 t0 = Trow[sl * 2];
    float4 t1 = Trow[sl * 2 + 1];
    uint4 hv;
    hv.x = h2u(__floats2half2_rn(wn * (a0 + t0.x), wn * (a1 + t0.y)));
    hv.y = h2u(__floats2half2_rn(wn * (a2 + t0.z), wn * (a3 + t0.w)));
    hv.z = h2u(__floats2half2_rn(wn * (a4 + t1.x), wn * (a5 + t1.y)));
    hv.w = h2u(__floats2half2_rn(wn * (a6 + t1.z), wn * (a7 + t1.w)));
    ((uint4*)(g_aggh + (long)n * HD))[sl] = hv;
}

// ---------- tensor-core GEMM + fused epilogue ----------
// 256 threads (8 warps), tile 128 rows x 128 cols, K chunked by 64.
__global__ void __launch_bounds__(256) k_gemm_tc(int layer,
                                                 const float* __restrict__ bias,
                                                 float* __restrict__ out,
                                                 int outoff) {
    __shared__ __half As[128][72];
    __shared__ __half Bs[64][136];
    __shared__ float bsm[HD];

    const __half* Wh = g_Wh + layer * HD * HD;
    int tid = threadIdx.x;
    int lane = tid & 31;
    int warp = tid >> 5;
    int row0 = blockIdx.x * 128;

    if (tid < HD) {
        bsm[tid] = bias[tid];
    }

    float acc[16][4];
#pragma unroll
    for (int t = 0; t < 16; t++) {
#pragma unroll
        for (int j = 0; j < 4; j++) {
            acc[t][j] = 0.f;
        }
    }

    for (int kc = 0; kc < 2; kc++) {
        int k0 = kc * 64;
        __syncthreads();
        for (int i = tid; i < 1024; i += 256) {
            int r = i >> 3;
            int q = i & 7;
            uint4 v = make_uint4(0u, 0u, 0u, 0u);
            int gr = row0 + r;
            if (gr < NN) {
                v = ((const uint4*)(g_aggh + (long)gr * HD + k0))[q];
            }
            *(uint4*)(&As[r][q * 8]) = v;
        }
        for (int i = tid; i < 1024; i += 256) {
            int r = i >> 4;
            int q = i & 15;
            uint4 v = ((const uint4*)(Wh + (long)(k0 + r) * HD))[q];
            *(uint4*)(&Bs[r][q * 8]) = v;
        }
        __syncthreads();

        int wr = warp * 16;
#pragma unroll
        for (int ks = 0; ks < 4; ks++) {
            unsigned va0, va1, va2, va3;
            ldsm_x4(va0, va1, va2, va3,
                    smem_u32(&As[wr + (lane & 15)][ks * 16 + (lane >> 4) * 8]));
#pragma unroll
            for (int nt = 0; nt < 8; nt++) {
                unsigned vb0, vb1, vb2, vb3;
                ldsm_x4_t(vb0, vb1, vb2, vb3,
                          smem_u32(&Bs[ks * 16 + (lane & 15)][nt * 16 + (lane >> 4) * 8]));
                mma16816(acc[nt * 2], va0, va1, va2, va3, vb0, vb1);
                mma16816(acc[nt * 2 + 1], va0, va1, va2, va3, vb2, vb3);
            }
        }
    }

    // epilogue: bias + leaky relu + row sumsq via quad shuffles
    int qr = lane >> 2;
    int qc = lane & 3;
    int r_lo = row0 + warp * 16 + qr;
    int r_hi = r_lo + 8;

    float ss0 = 0.f;
    float ss1 = 0.f;
#pragma unroll
    for (int t = 0; t < 16; t++) {
        int c0 = t * 8 + qc * 2;
        float b0 = bsm[c0];
        float b1 = bsm[c0 + 1];
        float v0 = acc[t][0] + b0;
        float v1 = acc[t][1] + b1;
        float v2 = acc[t][2] + b0;
        float v3 = acc[t][3] + b1;
        v0 = (v0 >= 0.f) ? v0 : (SLOPE * v0);
        v1 = (v1 >= 0.f) ? v1 : (SLOPE * v1);
        v2 = (v2 >= 0.f) ? v2 : (SLOPE * v2);
        v3 = (v3 >= 0.f) ? v3 : (SLOPE * v3);
        acc[t][0] = v0;
        acc[t][1] = v1;
        acc[t][2] = v2;
        acc[t][3] = v3;
        ss0 = fmaf(v0, v0, ss0);
        ss0 = fmaf(v1, v1, ss0);
        ss1 = fmaf(v2, v2, ss1);
        ss1 = fmaf(v3, v3, ss1);
    }
    ss0 += __shfl_xor_sync(0xffffffffu, ss0, 1);
    ss0 += __shfl_xor_sync(0xffffffffu, ss0, 2);
    ss1 += __shfl_xor_sync(0xffffffffu, ss1, 1);
    ss1 += __shfl_xor_sync(0xffffffffu, ss1, 2);
    float ri0 = 1.f / fmaxf(sqrtf(ss0), 1e-12f);
    float ri1 = 1.f / fmaxf(sqrtf(ss1), 1e-12f);

    if (r_lo < NN) {
        float* orow = out + (long)r_lo * OW + outoff;
        __half2* xrow = (__half2*)(g_xh + (long)r_lo * HD);
#pragma unroll
        for (int t = 0; t < 16; t++) {
            int c = t * 8 + qc * 2;
            *(float2*)(orow + c) = make_float2(acc[t][0] * ri0, acc[t][1] * ri0);
            xrow[c >> 1] = __floats2half2_rn(acc[t][0], acc[t][1]);
        }
    }
    if (r_hi < NN) {
        float* orow = out + (long)r_hi * OW + outoff;
        __half2* xrow = (__half2*)(g_xh + (long)r_hi * HD);
#pragma unroll
        for (int t = 0; t < 16; t++) {
            int c = t * 8 + qc * 2;
            *(float2*)(orow + c) = make_float2(acc[t][2] * ri1, acc[t][3] * ri1);
            xrow[c >> 1] = __floats2half2_rn(acc[t][2], acc[t][3]);
        }
    }
}

extern "C" void kernel_launch(void* const* d_in, const int* in_sizes, int n_in,
                              void* d_out, int out_size) {
    const float* user_embd  = (const float*)d_in[0];
    const float* item_embd  = (const float*)d_in[1];
    const float* time_table = (const float*)d_in[2];
    const float* Wsrc       = (const float*)d_in[3];
    const float* bsrc       = (const float*)d_in[4];
    const int*   user_idx   = (const int*)d_in[5];
    const int*   item_idx   = (const int*)d_in[6];
    const int*   time_seq   = (const int*)d_in[7];
    float* out = (float*)d_out;

    k_zero_deg<<<(NN + 255) / 256, 256>>>();
    k_hist<<<(NE + 255) / 256, 256>>>(user_idx, item_idx);
    k_scan1<<<SCAN_NB, SCAN_BS>>>();
    k_scan2<<<1, 256>>>();
    k_scan3<<<(NN + 255) / 256, 256>>>();
    k_scatter<<<(NE + 255) / 256, 256>>>(user_idx, item_idx, time_seq);

    k_init<<<(NN * HD + 255) / 256, 256>>>(user_embd, item_embd, Wsrc, out);

    k_aggT<<<(NN * 32 + 255) / 256, 256>>>(time_table);

    for (int l = 0; l < NL; l++) {
        k_aggx<<<(NN * 16 + 255) / 256, 256>>>();
        k_gemm_tc<<<(NN + 127) / 128, 256>>>(l, bsrc + l * HD, out, (l + 1) * HD);
    }
}

// round 7
// speedup vs baseline: 1.8712x; 1.0295x over previous
#include <cuda_runtime.h>
#include <cuda_fp16.h>
#include <cuda_bf16.h>

#define NU 100000
#define NI 50000
#define NN 150000
#define HD 128
#define NE 1000000
#define NE2 2000000
#define NL 3
#define SLOPE 0.2f
#define OW 512

#define SCAN_BS 1024
#define SCAN_NB 147

#define FUSED_SMEM 52736

// ---------- device scratch ----------
__device__ int    g_deg[NN];
__device__ int    g_rp[NN + 1];
__device__ int    g_cursor[NN];
__device__ float  g_dinv[NN];
__device__ int    g_partials[SCAN_NB + 1];
__device__ int2   g_edge2[NE2];
__device__ __half g_xhA[NN * HD];   // x buffer, parity 0
__device__ __half g_xhB[NN * HD];   // x buffer, parity 1
__device__ float  g_T[NN * HD];
__device__ __half g_Wh[NL * HD * HD];

// ---------- mma helpers ----------
__device__ __forceinline__ unsigned smem_u32(const void* p) {
    return (unsigned)__cvta_generic_to_shared(p);
}

__device__ __forceinline__ void ldsm_x4(unsigned& r0, unsigned& r1,
                                        unsigned& r2, unsigned& r3, unsigned a) {
    asm volatile("ldmatrix.sync.aligned.m8n8.x4.shared.b16 {%0,%1,%2,%3}, [%4];"
                 : "=r"(r0), "=r"(r1), "=r"(r2), "=r"(r3) : "r"(a));
}

__device__ __forceinline__ void ldsm_x4_t(unsigned& r0, unsigned& r1,
                                          unsigned& r2, unsigned& r3, unsigned a) {
    asm volatile("ldmatrix.sync.aligned.m8n8.x4.trans.shared.b16 {%0,%1,%2,%3}, [%4];"
                 : "=r"(r0), "=r"(r1), "=r"(r2), "=r"(r3) : "r"(a));
}

__device__ __forceinline__ void mma16816(float* d, unsigned a0, unsigned a1,
                                         unsigned a2, unsigned a3,
                                         unsigned b0, unsigned b1) {
    asm volatile("mma.sync.aligned.m16n8k16.row.col.f32.f16.f16.f32 "
                 "{%0,%1,%2,%3}, {%4,%5,%6,%7}, {%8,%9}, {%0,%1,%2,%3};"
                 : "+f"(d[0]), "+f"(d[1]), "+f"(d[2]), "+f"(d[3])
                 : "r"(a0), "r"(a1), "r"(a2), "r"(a3), "r"(b0), "r"(b1));
}

__device__ __forceinline__ unsigned h2u(__half2 h) {
    unsigned u;
    memcpy(&u, &h, 4);
    return u;
}

// ---------- graph build ----------
__global__ void k_zero_deg() {
    int i = blockIdx.x * blockDim.x + threadIdx.x;
    if (i < NN) g_deg[i] = 0;
}

__global__ void k_hist(const int* __restrict__ ui, const int* __restrict__ ii) {
    int e = blockIdx.x * blockDim.x + threadIdx.x;
    if (e < NE) {
        atomicAdd(&g_deg[ui[e]], 1);
        atomicAdd(&g_deg[ii[e] + NU], 1);
    }
}

__global__ void k_scan1() {
    __shared__ int sh[SCAN_BS];
    int i = blockIdx.x * SCAN_BS + threadIdx.x;
    int v = (i < NN) ? g_deg[i] : 0;
    sh[threadIdx.x] = v;
    __syncthreads();
    for (int off = 1; off < SCAN_BS; off <<= 1) {
        int t = (threadIdx.x >= off) ? sh[threadIdx.x - off] : 0;
        __syncthreads();
        sh[threadIdx.x] += t;
        __syncthreads();
    }
    if (i < NN) g_rp[i] = sh[threadIdx.x] - v;
    if (threadIdx.x == SCAN_BS - 1) g_partials[blockIdx.x] = sh[SCAN_BS - 1];
}

__global__ void k_scan2() {
    __shared__ int sh[256];
    int i = threadIdx.x;
    int v = (i < SCAN_NB) ? g_partials[i] : 0;
    sh[i] = v;
    __syncthreads();
    for (int off = 1; off < 256; off <<= 1) {
        int t = (i >= off) ? sh[i - off] : 0;
        __syncthreads();
        sh[i] += t;
        __syncthreads();
    }
    if (i < SCAN_NB) g_partials[i] = sh[i] - v;
}

__global__ void k_scan3() {
    int i = blockIdx.x * blockDim.x + threadIdx.x;
    if (i < NN) {
        int v = g_rp[i] + g_partials[i / SCAN_BS];
        g_rp[i] = v;
        g_cursor[i] = v;
        int d = g_deg[i];
        g_dinv[i] = rsqrtf((float)(d > 1 ? d : 1));
    }
    if (i == 0) g_rp[NN] = NE2;
}

__global__ void k_scatter(const int* __restrict__ ui, const int* __restrict__ ii,
                          const int* __restrict__ ts) {
    int e = blockIdx.x * blockDim.x + threadIdx.x;
    if (e < NE) {
        int u = ui[e];
        int it = ii[e] + NU;
        int t = ts[e];
        float wu = g_dinv[u];
        float wi = g_dinv[it];
        int p = atomicAdd(&g_cursor[u], 1);
        g_edge2[p] = make_int2(it | (t << 18), __float_as_int(wi));
        int q = atomicAdd(&g_cursor[it], 1);
        g_edge2[q] = make_int2(u | (t << 18), __float_as_int(wu));
    }
}

// ---------- init ----------
__global__ void k_init(const float* __restrict__ ue, const float* __restrict__ ie,
                       const float* __restrict__ Wsrc, float* __restrict__ out) {
    int i = blockIdx.x * blockDim.x + threadIdx.x;
    if (i < NN * HD) {
        int n = i >> 7;
        int j = i & 127;
        float v = (n < NU) ? ue[i] : ie[i - NU * HD];
        g_xhA[i] = __float2half(v);
        out[(long)n * OW + j] = v;
    }
    if (i < NL * HD * HD) {
        g_Wh[i] = __float2half(Wsrc[i]);
    }
}

// ---------- one-time time aggregation ----------
__global__ void k_aggT(const float* __restrict__ tt) {
    int gw = (blockIdx.x * blockDim.x + threadIdx.x) >> 5;
    int lane = threadIdx.x & 31;
    if (gw >= NN) return;
    int beg = g_rp[gw];
    int end = g_rp[gw + 1];
    const float4* t4 = (const float4*)tt;
    float4 acc = make_float4(0.f, 0.f, 0.f, 0.f);
    for (int e = beg; e < end; e++) {
        int2 ed = g_edge2[e];
        int t = ed.x >> 18;
        float w = __int_as_float(ed.y);
        float4 tv = __ldg(&t4[t * 32 + lane]);
        acc.x = fmaf(tv.x, w, acc.x);
        acc.y = fmaf(tv.y, w, acc.y);
        acc.z = fmaf(tv.z, w, acc.z);
        acc.w = fmaf(tv.w, w, acc.w);
    }
    ((float4*)g_T)[gw * 32 + lane] = acc;
}

// ---------- fused: aggregation + tensor-core GEMM + epilogue ----------
// 256 threads (8 warps). Block owns 128 contiguous node rows.
// Reads x from xin (parity), writes next-layer x to xout (other parity):
// no cross-block race within the launch.
__global__ void __launch_bounds__(256) k_fused(int layer,
                                               const __half* __restrict__ xin,
                                               __half* __restrict__ xout,
                                               const float* __restrict__ bias,
                                               float* __restrict__ out,
                                               int outoff) {
    extern __shared__ __half smem_dyn[];
    __half* As = smem_dyn;                       // [128][136]
    __half* Bs = smem_dyn + 128 * 136;           // [64][136]
    float*  bsm = (float*)(smem_dyn + 128 * 136 + 64 * 136);  // [128]

    const __half* Wh = g_Wh + layer * HD * HD;
    int tid = threadIdx.x;
    int lane = tid & 31;
    int warp = tid >> 5;
    int row0 = blockIdx.x * 128;

    if (tid < HD) {
        bsm[tid] = bias[tid];
    }

    // ---- phase 1: gather into As ----
    {
        int hw = tid >> 4;      // half-warp 0..15
        int sl = tid & 15;      // sub-lane 0..15
        const uint4* xh4 = (const uint4*)xin;
        for (int batch = 0; batch < 8; batch++) {
            int r = batch * 16 + hw;
            int n = row0 + r;
            float a0 = 0.f, a1 = 0.f, a2 = 0.f, a3 = 0.f;
            float a4 = 0.f, a5 = 0.f, a6 = 0.f, a7 = 0.f;
            uint4 hv = make_uint4(0u, 0u, 0u, 0u);
            if (n < NN) {
                int beg = g_rp[n];
                int end = g_rp[n + 1];
                for (int e = beg; e < end; e++) {
                    int2 ed = __ldg(&g_edge2[e]);
                    int src = ed.x & 0x3FFFF;
                    float w = __int_as_float(ed.y);
                    uint4 v = __ldg(&xh4[src * 16 + sl]);
                    float2 f0 = __half22float2(*(const __half2*)&v.x);
                    float2 f1 = __half22float2(*(const __half2*)&v.y);
                    float2 f2 = __half22float2(*(const __half2*)&v.z);
                    float2 f3 = __half22float2(*(const __half2*)&v.w);
                    a0 = fmaf(f0.x, w, a0);
                    a1 = fmaf(f0.y, w, a1);
                    a2 = fmaf(f1.x, w, a2);
                    a3 = fmaf(f1.y, w, a3);
                    a4 = fmaf(f2.x, w, a4);
                    a5 = fmaf(f2.y, w, a5);
                    a6 = fmaf(f3.x, w, a6);
                    a7 = fmaf(f3.y, w, a7);
                }
                float wn = g_dinv[n];
                const float4* Trow = (const float4*)(g_T + (long)n * HD);
                float4 t0 = Trow[sl * 2];
                float4 t1 = Trow[sl * 2 + 1];
                hv.x = h2u(__floats2half2_rn(wn * (a0 + t0.x), wn * (a1 + t0.y)));
                hv.y = h2u(__floats2half2_rn(wn * (a2 + t0.z), wn * (a3 + t0.w)));
                hv.z = h2u(__floats2half2_rn(wn * (a4 + t1.x), wn * (a5 + t1.y)));
                hv.w = h2u(__floats2half2_rn(wn * (a6 + t1.z), wn * (a7 + t1.w)));
            }
            *(uint4*)(&As[r * 136 + sl * 8]) = hv;
        }
    }

    // ---- phase 2: HMMA ----
    float acc[16][4];
#pragma unroll
    for (int t = 0; t < 16; t++) {
#pragma unroll
        for (int j = 0; j < 4; j++) {
            acc[t][j] = 0.f;
        }
    }

    int wr = warp * 16;
    for (int kc = 0; kc < 2; kc++) {
        for (int i = tid; i < 1024; i += 256) {
            int r = i >> 4;
            int q = i & 15;
            uint4 v = ((const uint4*)(Wh + (long)(kc * 64 + r) * HD))[q];
            *(uint4*)(&Bs[r * 136 + q * 8]) = v;
        }
        __syncthreads();
#pragma unroll
        for (int ks = 0; ks < 4; ks++) {
            int kk = kc * 64 + ks * 16;
            unsigned va0, va1, va2, va3;
            ldsm_x4(va0, va1, va2, va3,
                    smem_u32(&As[(wr + (lane & 15)) * 136 + kk + (lane >> 4) * 8]));
#pragma unroll
            for (int nt = 0; nt < 8; nt++) {
                unsigned vb0, vb1, vb2, vb3;
                ldsm_x4_t(vb0, vb1, vb2, vb3,
                          smem_u32(&Bs[(ks * 16 + (lane & 15)) * 136 + nt * 16 + (lane >> 4) * 8]));
                mma16816(acc[nt * 2], va0, va1, va2, va3, vb0, vb1);
                mma16816(acc[nt * 2 + 1], va0, va1, va2, va3, vb2, vb3);
            }
        }
        __syncthreads();
    }

    // ---- phase 3: epilogue ----
    int qr = lane >> 2;
    int qc = lane & 3;
    int r_lo = row0 + warp * 16 + qr;
    int r_hi = r_lo + 8;

    float ss0 = 0.f;
    float ss1 = 0.f;
#pragma unroll
    for (int t = 0; t < 16; t++) {
        int c0 = t * 8 + qc * 2;
        float b0 = bsm[c0];
        float b1 = bsm[c0 + 1];
        float v0 = acc[t][0] + b0;
        float v1 = acc[t][1] + b1;
        float v2 = acc[t][2] + b0;
        float v3 = acc[t][3] + b1;
        v0 = (v0 >= 0.f) ? v0 : (SLOPE * v0);
        v1 = (v1 >= 0.f) ? v1 : (SLOPE * v1);
        v2 = (v2 >= 0.f) ? v2 : (SLOPE * v2);
        v3 = (v3 >= 0.f) ? v3 : (SLOPE * v3);
        acc[t][0] = v0;
        acc[t][1] = v1;
        acc[t][2] = v2;
        acc[t][3] = v3;
        ss0 = fmaf(v0, v0, ss0);
        ss0 = fmaf(v1, v1, ss0);
        ss1 = fmaf(v2, v2, ss1);
        ss1 = fmaf(v3, v3, ss1);
    }
    ss0 += __shfl_xor_sync(0xffffffffu, ss0, 1);
    ss0 += __shfl_xor_sync(0xffffffffu, ss0, 2);
    ss1 += __shfl_xor_sync(0xffffffffu, ss1, 1);
    ss1 += __shfl_xor_sync(0xffffffffu, ss1, 2);
    float ri0 = 1.f / fmaxf(sqrtf(ss0), 1e-12f);
    float ri1 = 1.f / fmaxf(sqrtf(ss1), 1e-12f);

    if (r_lo < NN) {
        float* orow = out + (long)r_lo * OW + outoff;
        __half2* xrow = (__half2*)(xout + (long)r_lo * HD);
#pragma unroll
        for (int t = 0; t < 16; t++) {
            int c = t * 8 + qc * 2;
            *(float2*)(orow + c) = make_float2(acc[t][0] * ri0, acc[t][1] * ri0);
            xrow[c >> 1] = __floats2half2_rn(acc[t][0], acc[t][1]);
        }
    }
    if (r_hi < NN) {
        float* orow = out + (long)r_hi * OW + outoff;
        __half2* xrow = (__half2*)(xout + (long)r_hi * HD);
#pragma unroll
        for (int t = 0; t < 16; t++) {
            int c = t * 8 + qc * 2;
            *(float2*)(orow + c) = make_float2(acc[t][2] * ri1, acc[t][3] * ri1);
            xrow[c >> 1] = __floats2half2_rn(acc[t][2], acc[t][3]);
        }
    }
}

extern "C" void kernel_launch(void* const* d_in, const int* in_sizes, int n_in,
                              void* d_out, int out_size) {
    const float* user_embd  = (const float*)d_in[0];
    const float* item_embd  = (const float*)d_in[1];
    const float* time_table = (const float*)d_in[2];
    const float* Wsrc       = (const float*)d_in[3];
    const float* bsrc       = (const float*)d_in[4];
    const int*   user_idx   = (const int*)d_in[5];
    const int*   item_idx   = (const int*)d_in[6];
    const int*   time_seq   = (const int*)d_in[7];
    float* out = (float*)d_out;

    static __half* xbuf[2] = {nullptr, nullptr};
    static int smem_cfg = 0;
    if (!smem_cfg) {
        cudaFuncSetAttribute(k_fused, cudaFuncAttributeMaxDynamicSharedMemorySize,
                             FUSED_SMEM);
        cudaGetSymbolAddress((void**)&xbuf[0], g_xhA);
        cudaGetSymbolAddress((void**)&xbuf[1], g_xhB);
        smem_cfg = 1;
    }

    k_zero_deg<<<(NN + 255) / 256, 256>>>();
    k_hist<<<(NE + 255) / 256, 256>>>(user_idx, item_idx);
    k_scan1<<<SCAN_NB, SCAN_BS>>>();
    k_scan2<<<1, 256>>>();
    k_scan3<<<(NN + 255) / 256, 256>>>();
    k_scatter<<<(NE + 255) / 256, 256>>>(user_idx, item_idx, time_seq);

    k_init<<<(NN * HD + 255) / 256, 256>>>(user_embd, item_embd, Wsrc, out);

    k_aggT<<<(NN * 32 + 255) / 256, 256>>>(time_table);

    for (int l = 0; l < NL; l++) {
        k_fused<<<(NN + 127) / 128, 256, FUSED_SMEM>>>(l, xbuf[l & 1],
                                                       xbuf[(l + 1) & 1],
                                                       bsrc + l * HD, out,
                                                       (l + 1) * HD);
    }
}